// round 1
// baseline (speedup 1.0000x reference)
#include <cuda_runtime.h>
#include <math.h>

// ---------------------------------------------------------------------------
// Problem constants (fixed shapes)
// ---------------------------------------------------------------------------
#define B_     8
#define N_     2048
#define M_     32768
#define QD_    512
#define DR_    256
#define D_     512
#define H_     8
#define DH_    64
#define INNER_ 512
#define TOPK_  8
#define SCALE_ 0.125f

#define DIST_BLOCKS 64   // blocks per batch for the distance scan

// ---------------------------------------------------------------------------
// Scratch (device globals: allocation-free per harness rules)
// ---------------------------------------------------------------------------
__device__ float g_q[B_ * N_ * INNER_];     // q = x @ Wq
__device__ float g_att[B_ * N_ * INNER_];   // attention output (pre-Wout)
__device__ float g_e0[B_ * DR_];            // query embedding of token 0
__device__ float g_cand_d2[B_ * DIST_BLOCKS * TOPK_];
__device__ int   g_cand_idx[B_ * DIST_BLOCKS * TOPK_];
__device__ int   g_topk_idx[B_ * TOPK_];
__device__ float g_k[B_ * TOPK_ * INNER_];
__device__ float g_v[B_ * TOPK_ * INNER_];

// ---------------------------------------------------------------------------
// Kernel 1: e0[b,:] = (x[b,0,:] @ Wq) @ We        (8 x 256, tiny)
// ---------------------------------------------------------------------------
__global__ void e0_kernel(const float* __restrict__ x,
                          const float* __restrict__ Wq,
                          const float* __restrict__ We) {
    int b = blockIdx.x;
    int tid = threadIdx.x;  // 512 threads
    __shared__ float xs[QD_];
    __shared__ float q0[QD_];

    xs[tid] = x[(long)b * N_ * QD_ + tid];
    __syncthreads();

    float a0 = 0.f, a1 = 0.f, a2 = 0.f, a3 = 0.f;
#pragma unroll 4
    for (int c = 0; c < QD_; c += 4) {
        a0 += xs[c + 0] * Wq[(c + 0) * INNER_ + tid];
        a1 += xs[c + 1] * Wq[(c + 1) * INNER_ + tid];
        a2 += xs[c + 2] * Wq[(c + 2) * INNER_ + tid];
        a3 += xs[c + 3] * Wq[(c + 3) * INNER_ + tid];
    }
    q0[tid] = (a0 + a1) + (a2 + a3);
    __syncthreads();

    if (tid < DR_) {
        a0 = a1 = a2 = a3 = 0.f;
#pragma unroll 4
        for (int c = 0; c < INNER_; c += 4) {
            a0 += q0[c + 0] * We[(c + 0) * DR_ + tid];
            a1 += q0[c + 1] * We[(c + 1) * DR_ + tid];
            a2 += q0[c + 2] * We[(c + 2) * DR_ + tid];
            a3 += q0[c + 3] * We[(c + 3) * DR_ + tid];
        }
        g_e0[b * DR_ + tid] = (a0 + a1) + (a2 + a3);
    }
}

// ---------------------------------------------------------------------------
// Kernel 2: per-chunk distance scan + local top-8
// grid (DIST_BLOCKS, B), block 256 (8 warps). Each warp handles 64 rows.
// ---------------------------------------------------------------------------
__global__ void dist_topk_kernel(const float* __restrict__ ctx) {
    int b = blockIdx.y;
    int chunk = blockIdx.x;
    int tid = threadIdx.x;
    int warp = tid >> 5, lane = tid & 31;

    __shared__ float es[DR_];
    __shared__ float s_d2[8][TOPK_];
    __shared__ int   s_ix[8][TOPK_];

    if (tid < DR_) es[tid] = g_e0[b * DR_ + tid];
    __syncthreads();

    const float4* e4 = (const float4*)es;
    float4 ea = e4[lane];
    float4 eb = e4[lane + 32];

    float best[TOPK_];
    int   bidx[TOPK_];
#pragma unroll
    for (int i = 0; i < TOPK_; i++) { best[i] = 3.0e38f; bidx[i] = -1; }

    int row0 = chunk * 512 + warp * 64;
    for (int r = 0; r < 64; r++) {
        int row = row0 + r;
        const float4* crow = (const float4*)(ctx + ((long)b * M_ + row) * D_);
        float4 ca = crow[lane];
        float4 cb = crow[lane + 32];
        float dx, d2 = 0.f;
        dx = ca.x - ea.x; d2 += dx * dx;
        dx = ca.y - ea.y; d2 += dx * dx;
        dx = ca.z - ea.z; d2 += dx * dx;
        dx = ca.w - ea.w; d2 += dx * dx;
        dx = cb.x - eb.x; d2 += dx * dx;
        dx = cb.y - eb.y; d2 += dx * dx;
        dx = cb.z - eb.z; d2 += dx * dx;
        dx = cb.w - eb.w; d2 += dx * dx;
#pragma unroll
        for (int off = 16; off; off >>= 1)
            d2 += __shfl_down_sync(0xffffffffu, d2, off);
        if (lane == 0 && d2 < best[TOPK_ - 1]) {
            int p = TOPK_ - 1;
            while (p > 0 && best[p - 1] > d2) {
                best[p] = best[p - 1]; bidx[p] = bidx[p - 1]; p--;
            }
            best[p] = d2; bidx[p] = row;
        }
    }

    if (lane == 0) {
#pragma unroll
        for (int i = 0; i < TOPK_; i++) { s_d2[warp][i] = best[i]; s_ix[warp][i] = bidx[i]; }
    }
    __syncthreads();

    if (tid == 0) {
        float fb[TOPK_]; int fi[TOPK_];
#pragma unroll
        for (int i = 0; i < TOPK_; i++) { fb[i] = 3.0e38f; fi[i] = -1; }
        for (int w = 0; w < 8; w++)
            for (int i = 0; i < TOPK_; i++) {
                float d2 = s_d2[w][i];
                if (d2 < fb[TOPK_ - 1]) {
                    int ix = s_ix[w][i];
                    int p = TOPK_ - 1;
                    while (p > 0 && fb[p - 1] > d2) {
                        fb[p] = fb[p - 1]; fi[p] = fi[p - 1]; p--;
                    }
                    fb[p] = d2; fi[p] = ix;
                }
            }
        int off = (b * DIST_BLOCKS + chunk) * TOPK_;
        for (int i = 0; i < TOPK_; i++) { g_cand_d2[off + i] = fb[i]; g_cand_idx[off + i] = fi[i]; }
    }
}

// ---------------------------------------------------------------------------
// Kernel 3: merge per-block candidates into global per-batch top-8
// ---------------------------------------------------------------------------
__global__ void topk_merge_kernel() {
    int b = blockIdx.x;
    if (threadIdx.x != 0) return;
    float fb[TOPK_]; int fi[TOPK_];
#pragma unroll
    for (int i = 0; i < TOPK_; i++) { fb[i] = 3.0e38f; fi[i] = -1; }
    int base = b * DIST_BLOCKS * TOPK_;
    for (int c = 0; c < DIST_BLOCKS * TOPK_; c++) {
        float d2 = g_cand_d2[base + c];
        if (d2 < fb[TOPK_ - 1]) {
            int ix = g_cand_idx[base + c];
            int p = TOPK_ - 1;
            while (p > 0 && fb[p - 1] > d2) {
                fb[p] = fb[p - 1]; fi[p] = fi[p - 1]; p--;
            }
            fb[p] = d2; fi[p] = ix;
        }
    }
    for (int i = 0; i < TOPK_; i++) g_topk_idx[b * TOPK_ + i] = fi[i];
}

// ---------------------------------------------------------------------------
// Kernel 4: gather selected rows; k = labels@Wk, v = reps@Wv
// grid (B, TOPK), 256 threads
// ---------------------------------------------------------------------------
__global__ void kv_kernel(const float* __restrict__ ctx,
                          const float* __restrict__ Wk,
                          const float* __restrict__ Wv) {
    int b = blockIdx.x, j = blockIdx.y;
    int tid = threadIdx.x;  // 256
    __shared__ float reps[DR_];
    __shared__ float labels[DR_];

    int row = g_topk_idx[b * TOPK_ + j];
    const float* crow = ctx + ((long)b * M_ + row) * D_;
    reps[tid] = crow[tid];
    labels[tid] = crow[DR_ + tid];
    __syncthreads();

    float k0 = 0.f, k1 = 0.f, v0 = 0.f, v1 = 0.f;
#pragma unroll 8
    for (int c = 0; c < DR_; c++) {
        float l = labels[c], r = reps[c];
        k0 += l * Wk[c * INNER_ + tid];
        k1 += l * Wk[c * INNER_ + tid + 256];
        v0 += r * Wv[c * INNER_ + tid];
        v1 += r * Wv[c * INNER_ + tid + 256];
    }
    int off = (b * TOPK_ + j) * INNER_;
    g_k[off + tid] = k0; g_k[off + tid + 256] = k1;
    g_v[off + tid] = v0; g_v[off + tid + 256] = v1;
}

// ---------------------------------------------------------------------------
// Kernel 5: attention. grid (32, B), 256 threads (8 warps, 8 tokens each).
// Lane l owns head h=l>>2, 16 dims. k/v in smem with 16-float blocks padded
// to 20 words (lane stride 20 -> conflict-free LDS.128).
// ---------------------------------------------------------------------------
__global__ void attn_kernel() {
    int b = blockIdx.y;
    int chunk = blockIdx.x;
    int tid = threadIdx.x;
    __shared__ float ks[TOPK_ * 640];
    __shared__ float vs[TOPK_ * 640];

    for (int idx = tid; idx < TOPK_ * INNER_; idx += 256) {
        int j = idx >> 9, d = idx & 511;
        int w = j * 640 + (d >> 4) * 20 + (d & 15);
        ks[w] = g_k[(b * TOPK_ + j) * INNER_ + d];
        vs[w] = g_v[(b * TOPK_ + j) * INNER_ + d];
    }
    __syncthreads();

    int warp = tid >> 5, lane = tid & 31;
    int qoff = lane * 16;  // == h*64 + dp*16

    for (int t = 0; t < 8; t++) {
        int n = chunk * 64 + warp * 8 + t;
        const float* qrow = g_q + ((long)b * N_ + n) * INNER_;
        float4 q0 = *(const float4*)(qrow + qoff + 0);
        float4 q1 = *(const float4*)(qrow + qoff + 4);
        float4 q2 = *(const float4*)(qrow + qoff + 8);
        float4 q3 = *(const float4*)(qrow + qoff + 12);

        float sim[TOPK_];
#pragma unroll
        for (int j = 0; j < TOPK_; j++) {
            const float* kp = ks + j * 640 + lane * 20;
            float4 k0 = *(const float4*)(kp + 0);
            float4 k1 = *(const float4*)(kp + 4);
            float4 k2 = *(const float4*)(kp + 8);
            float4 k3 = *(const float4*)(kp + 12);
            float p = q0.x * k0.x + q0.y * k0.y + q0.z * k0.z + q0.w * k0.w
                    + q1.x * k1.x + q1.y * k1.y + q1.z * k1.z + q1.w * k1.w
                    + q2.x * k2.x + q2.y * k2.y + q2.z * k2.z + q2.w * k2.w
                    + q3.x * k3.x + q3.y * k3.y + q3.z * k3.z + q3.w * k3.w;
            p += __shfl_xor_sync(0xffffffffu, p, 1);
            p += __shfl_xor_sync(0xffffffffu, p, 2);
            sim[j] = p * SCALE_;
        }
        float m = sim[0];
#pragma unroll
        for (int j = 1; j < TOPK_; j++) m = fmaxf(m, sim[j]);
        float e[TOPK_], s = 0.f;
#pragma unroll
        for (int j = 0; j < TOPK_; j++) { e[j] = __expf(sim[j] - m); s += e[j]; }
        float inv = 1.f / s;

        float4 o0 = {0, 0, 0, 0}, o1 = {0, 0, 0, 0}, o2 = {0, 0, 0, 0}, o3 = {0, 0, 0, 0};
#pragma unroll
        for (int j = 0; j < TOPK_; j++) {
            float a = e[j] * inv;
            const float* vp = vs + j * 640 + lane * 20;
            float4 v0 = *(const float4*)(vp + 0);
            float4 v1 = *(const float4*)(vp + 4);
            float4 v2 = *(const float4*)(vp + 8);
            float4 v3 = *(const float4*)(vp + 12);
            o0.x += a * v0.x; o0.y += a * v0.y; o0.z += a * v0.z; o0.w += a * v0.w;
            o1.x += a * v1.x; o1.y += a * v1.y; o1.z += a * v1.z; o1.w += a * v1.w;
            o2.x += a * v2.x; o2.y += a * v2.y; o2.z += a * v2.z; o2.w += a * v2.w;
            o3.x += a * v3.x; o3.y += a * v3.y; o3.z += a * v3.z; o3.w += a * v3.w;
        }
        float* orow = g_att + ((long)b * N_ + n) * INNER_ + qoff;
        *(float4*)(orow + 0) = o0;
        *(float4*)(orow + 4) = o1;
        *(float4*)(orow + 8) = o2;
        *(float4*)(orow + 12) = o3;
    }
}

// ---------------------------------------------------------------------------
// Kernel 6: fp32 GEMM, C[Mr,512] = A[Mr,512] @ W[512,512] (+ bias)
// 128x128 tile, BK=8, 256 threads, 8x8 microtile (2x 4-row x 2x 4-col frags),
// double-buffered smem.
// ---------------------------------------------------------------------------
__global__ void __launch_bounds__(256, 2)
gemm512(const float* __restrict__ A, const float* __restrict__ W,
        float* __restrict__ C, const float* __restrict__ bias) {
    __shared__ float As[2][8][128];
    __shared__ float Bs[2][8][128];

    int tid = threadIdx.x;
    int bm = blockIdx.y * 128;
    int bn = blockIdx.x * 128;

    int arow = tid >> 1, acol = (tid & 1) * 4;
    int brow = tid >> 5, bcol = (tid & 31) * 4;

    const float* Aptr = A + (long)(bm + arow) * 512 + acol;
    const float* Bptr = W + (long)brow * 512 + bn + bcol;

    float4 aR = *(const float4*)Aptr;
    float4 bR = *(const float4*)Bptr;
    As[0][acol + 0][arow] = aR.x;
    As[0][acol + 1][arow] = aR.y;
    As[0][acol + 2][arow] = aR.z;
    As[0][acol + 3][arow] = aR.w;
    *(float4*)&Bs[0][brow][bcol] = bR;
    __syncthreads();

    float acc[8][8];
#pragma unroll
    for (int i = 0; i < 8; i++)
#pragma unroll
        for (int j = 0; j < 8; j++) acc[i][j] = 0.f;

    int trA = (tid >> 4) * 4;
    int tcB = (tid & 15) * 4;
    int cur = 0;

    for (int kt = 0; kt < 64; kt++) {
        if (kt < 63) {
            aR = *(const float4*)(Aptr + (kt + 1) * 8);
            bR = *(const float4*)(Bptr + (long)(kt + 1) * 8 * 512);
        }
#pragma unroll
        for (int kk = 0; kk < 8; kk++) {
            float4 a0 = *(const float4*)&As[cur][kk][trA];
            float4 a1 = *(const float4*)&As[cur][kk][trA + 64];
            float4 b0 = *(const float4*)&Bs[cur][kk][tcB];
            float4 b1 = *(const float4*)&Bs[cur][kk][tcB + 64];
            float av[8] = {a0.x, a0.y, a0.z, a0.w, a1.x, a1.y, a1.z, a1.w};
            float bv[8] = {b0.x, b0.y, b0.z, b0.w, b1.x, b1.y, b1.z, b1.w};
#pragma unroll
            for (int i = 0; i < 8; i++)
#pragma unroll
                for (int j = 0; j < 8; j++) acc[i][j] += av[i] * bv[j];
        }
        if (kt < 63) {
            int nx = cur ^ 1;
            As[nx][acol + 0][arow] = aR.x;
            As[nx][acol + 1][arow] = aR.y;
            As[nx][acol + 2][arow] = aR.z;
            As[nx][acol + 3][arow] = aR.w;
            *(float4*)&Bs[nx][brow][bcol] = bR;
            __syncthreads();
            cur = nx;
        }
    }

    float bv[8];
    if (bias) {
#pragma unroll
        for (int j = 0; j < 4; j++) {
            bv[j] = bias[bn + tcB + j];
            bv[4 + j] = bias[bn + tcB + 64 + j];
        }
    } else {
#pragma unroll
        for (int j = 0; j < 8; j++) bv[j] = 0.f;
    }

#pragma unroll
    for (int i = 0; i < 8; i++) {
        int row = bm + trA + ((i < 4) ? i : 64 + (i - 4));
        float* crow = C + (long)row * 512 + bn;
        float4 c0 = {acc[i][0] + bv[0], acc[i][1] + bv[1], acc[i][2] + bv[2], acc[i][3] + bv[3]};
        float4 c1 = {acc[i][4] + bv[4], acc[i][5] + bv[5], acc[i][6] + bv[6], acc[i][7] + bv[7]};
        *(float4*)(crow + tcB) = c0;
        *(float4*)(crow + tcB + 64) = c1;
    }
}

// ---------------------------------------------------------------------------
// Launch
// ---------------------------------------------------------------------------
extern "C" void kernel_launch(void* const* d_in, const int* in_sizes, int n_in,
                              void* d_out, int out_size) {
    const float* x    = (const float*)d_in[0];
    const float* ctx  = (const float*)d_in[1];
    const float* Wq   = (const float*)d_in[2];
    const float* Wk   = (const float*)d_in[3];
    const float* Wv   = (const float*)d_in[4];
    const float* We   = (const float*)d_in[5];
    const float* Wout = (const float*)d_in[6];
    const float* bout = (const float*)d_in[7];
    float* out = (float*)d_out;

    float* qbuf = nullptr;
    float* attbuf = nullptr;
    cudaGetSymbolAddress((void**)&qbuf, g_q);
    cudaGetSymbolAddress((void**)&attbuf, g_att);

    // retrieval path (independent of big GEMM except ordering)
    e0_kernel<<<B_, 512>>>(x, Wq, We);
    dist_topk_kernel<<<dim3(DIST_BLOCKS, B_), 256>>>(ctx);
    topk_merge_kernel<<<B_, 32>>>();
    kv_kernel<<<dim3(B_, TOPK_), 256>>>(ctx, Wk, Wv);

    // q = x @ Wq
    gemm512<<<dim3(4, 128), 256>>>(x, Wq, qbuf, nullptr);

    // attention over the 8 retrieved kv pairs
    attn_kernel<<<dim3(32, B_), 256>>>();

    // out = att @ Wout + bout
    gemm512<<<dim3(4, 128), 256>>>(attbuf, Wout, out, bout);
}

// round 2
// speedup vs baseline: 1.5318x; 1.5318x over previous
#include <cuda_runtime.h>
#include <math.h>

// ---------------------------------------------------------------------------
// Problem constants
// ---------------------------------------------------------------------------
#define B_     8
#define N_     2048
#define M_     32768
#define QD_    512
#define DR_    256
#define D_     512
#define H_     8
#define DH_    64
#define INNER_ 512
#define TOPK_  8
#define SCALE_ 0.125f

#define DIST_BLOCKS 64

// ---------------------------------------------------------------------------
// Scratch (device globals)
// ---------------------------------------------------------------------------
__device__ float g_e0[B_ * DR_];
__device__ float g_cand_d2[B_ * DIST_BLOCKS * TOPK_];
__device__ int   g_cand_idx[B_ * DIST_BLOCKS * TOPK_];
__device__ int   g_topk_idx[B_ * TOPK_];
__device__ float g_WqT[QD_ * INNER_];          // WqT[i][p] = Wq[p][i]
__device__ float g_kappa[B_ * QD_ * 64];       // [b][p][c], c = j*8+h  (SCALE folded in)
__device__ float g_vw[B_ * 64 * INNER_];       // [b][c][o], c = j*8+h
__device__ float g_a[B_ * N_ * 64];            // attention weights [b][n][c], c=j*8+h

// ---------------------------------------------------------------------------
// Kernel 0: transpose Wq (512x512) -> g_WqT
// ---------------------------------------------------------------------------
__global__ void transpose512(const float* __restrict__ Wq) {
    __shared__ float tile[32][33];
    int bx = blockIdx.x * 32, by = blockIdx.y * 32;
    int tx = threadIdx.x & 31, ty = threadIdx.x >> 5;  // 256 threads: 8 rows/iter
#pragma unroll
    for (int r = ty; r < 32; r += 8)
        tile[r][tx] = Wq[(by + r) * 512 + bx + tx];
    __syncthreads();
#pragma unroll
    for (int r = ty; r < 32; r += 8)
        g_WqT[(bx + r) * 512 + by + tx] = tile[tx][r];
}

// ---------------------------------------------------------------------------
// Kernel 1: e0[b,:] = (x[b,0,:] @ Wq) @ We
// ---------------------------------------------------------------------------
__global__ void e0_kernel(const float* __restrict__ x,
                          const float* __restrict__ Wq,
                          const float* __restrict__ We) {
    int b = blockIdx.x;
    int tid = threadIdx.x;  // 512
    __shared__ float xs[QD_];
    __shared__ float q0[QD_];

    xs[tid] = x[(long)b * N_ * QD_ + tid];
    __syncthreads();

    float a0 = 0.f, a1 = 0.f, a2 = 0.f, a3 = 0.f;
#pragma unroll 4
    for (int c = 0; c < QD_; c += 4) {
        a0 += xs[c + 0] * Wq[(c + 0) * INNER_ + tid];
        a1 += xs[c + 1] * Wq[(c + 1) * INNER_ + tid];
        a2 += xs[c + 2] * Wq[(c + 2) * INNER_ + tid];
        a3 += xs[c + 3] * Wq[(c + 3) * INNER_ + tid];
    }
    q0[tid] = (a0 + a1) + (a2 + a3);
    __syncthreads();

    if (tid < DR_) {
        a0 = a1 = a2 = a3 = 0.f;
#pragma unroll 4
        for (int c = 0; c < INNER_; c += 4) {
            a0 += q0[c + 0] * We[(c + 0) * DR_ + tid];
            a1 += q0[c + 1] * We[(c + 1) * DR_ + tid];
            a2 += q0[c + 2] * We[(c + 2) * DR_ + tid];
            a3 += q0[c + 3] * We[(c + 3) * DR_ + tid];
        }
        g_e0[b * DR_ + tid] = (a0 + a1) + (a2 + a3);
    }
}

// ---------------------------------------------------------------------------
// Kernel 2: distance scan + local top-8  (grid (64, B), 256 thr)
// ---------------------------------------------------------------------------
__global__ void dist_topk_kernel(const float* __restrict__ ctx) {
    int b = blockIdx.y;
    int chunk = blockIdx.x;
    int tid = threadIdx.x;
    int warp = tid >> 5, lane = tid & 31;

    __shared__ float es[DR_];
    __shared__ float s_d2[8][TOPK_];
    __shared__ int   s_ix[8][TOPK_];

    if (tid < DR_) es[tid] = g_e0[b * DR_ + tid];
    __syncthreads();

    const float4* e4 = (const float4*)es;
    float4 ea = e4[lane];
    float4 eb = e4[lane + 32];

    float best[TOPK_];
    int   bidx[TOPK_];
#pragma unroll
    for (int i = 0; i < TOPK_; i++) { best[i] = 3.0e38f; bidx[i] = -1; }

    int row0 = chunk * 512 + warp * 64;
    for (int r = 0; r < 64; r++) {
        int row = row0 + r;
        const float4* crow = (const float4*)(ctx + ((long)b * M_ + row) * D_);
        float4 ca = crow[lane];
        float4 cb = crow[lane + 32];
        float dx, d2 = 0.f;
        dx = ca.x - ea.x; d2 += dx * dx;
        dx = ca.y - ea.y; d2 += dx * dx;
        dx = ca.z - ea.z; d2 += dx * dx;
        dx = ca.w - ea.w; d2 += dx * dx;
        dx = cb.x - eb.x; d2 += dx * dx;
        dx = cb.y - eb.y; d2 += dx * dx;
        dx = cb.z - eb.z; d2 += dx * dx;
        dx = cb.w - eb.w; d2 += dx * dx;
#pragma unroll
        for (int off = 16; off; off >>= 1)
            d2 += __shfl_down_sync(0xffffffffu, d2, off);
        if (lane == 0 && d2 < best[TOPK_ - 1]) {
            int p = TOPK_ - 1;
            while (p > 0 && best[p - 1] > d2) {
                best[p] = best[p - 1]; bidx[p] = bidx[p - 1]; p--;
            }
            best[p] = d2; bidx[p] = row;
        }
    }

    if (lane == 0) {
#pragma unroll
        for (int i = 0; i < TOPK_; i++) { s_d2[warp][i] = best[i]; s_ix[warp][i] = bidx[i]; }
    }
    __syncthreads();

    if (tid == 0) {
        float fb[TOPK_]; int fi[TOPK_];
#pragma unroll
        for (int i = 0; i < TOPK_; i++) { fb[i] = 3.0e38f; fi[i] = -1; }
        for (int w = 0; w < 8; w++)
            for (int i = 0; i < TOPK_; i++) {
                float d2 = s_d2[w][i];
                if (d2 < fb[TOPK_ - 1]) {
                    int ix = s_ix[w][i];
                    int p = TOPK_ - 1;
                    while (p > 0 && fb[p - 1] > d2) {
                        fb[p] = fb[p - 1]; fi[p] = fi[p - 1]; p--;
                    }
                    fb[p] = d2; fi[p] = ix;
                }
            }
        int off = (b * DIST_BLOCKS + chunk) * TOPK_;
        for (int i = 0; i < TOPK_; i++) { g_cand_d2[off + i] = fb[i]; g_cand_idx[off + i] = fi[i]; }
    }
}

// ---------------------------------------------------------------------------
// Kernel 3: merge candidates -> global per-batch top-8
// ---------------------------------------------------------------------------
__global__ void topk_merge_kernel() {
    int b = blockIdx.x;
    if (threadIdx.x != 0) return;
    float fb[TOPK_]; int fi[TOPK_];
#pragma unroll
    for (int i = 0; i < TOPK_; i++) { fb[i] = 3.0e38f; fi[i] = -1; }
    int base = b * DIST_BLOCKS * TOPK_;
    for (int c = 0; c < DIST_BLOCKS * TOPK_; c++) {
        float d2 = g_cand_d2[base + c];
        if (d2 < fb[TOPK_ - 1]) {
            int ix = g_cand_idx[base + c];
            int p = TOPK_ - 1;
            while (p > 0 && fb[p - 1] > d2) {
                fb[p] = fb[p - 1]; fi[p] = fi[p - 1]; p--;
            }
            fb[p] = d2; fi[p] = ix;
        }
    }
    for (int i = 0; i < TOPK_; i++) g_topk_idx[b * TOPK_ + i] = fi[i];
}

// ---------------------------------------------------------------------------
// Kernel 4 (fused): for each (b,j): gather row; k=labels@Wk; v=reps@Wv;
//   kappa[b,p,j*8+h] = SCALE * sum_d Wq[p,h*64+d]*k[h*64+d]   (via WqT)
//   vw[b,j*8+h,o]    = sum_d v[h*64+d]*Wout[h*64+d,o]
// grid 64 (b*8+j), 512 threads
// ---------------------------------------------------------------------------
__global__ void __launch_bounds__(512)
kvkv_kernel(const float* __restrict__ ctx,
            const float* __restrict__ Wk,
            const float* __restrict__ Wv,
            const float* __restrict__ Wout) {
    int bj = blockIdx.x;
    int b = bj >> 3, j = bj & 7;
    int tid = threadIdx.x;  // 512

    __shared__ float labels[DR_];
    __shared__ float reps[DR_];
    __shared__ float kvec[INNER_];
    __shared__ float vvec[INNER_];

    int row = g_topk_idx[bj];
    const float* crow = ctx + ((long)b * M_ + row) * D_;
    if (tid < 256) reps[tid] = crow[tid];
    else           labels[tid - 256] = crow[tid];
    __syncthreads();

    // k and v columns
    {
        float ak = 0.f, av = 0.f;
#pragma unroll 8
        for (int r = 0; r < DR_; r++) {
            float l = labels[r], rr = reps[r];
            ak += l * Wk[r * INNER_ + tid];
            av += rr * Wv[r * INNER_ + tid];
        }
        kvec[tid] = ak;
        vvec[tid] = av;
    }
    __syncthreads();

    // kappa: thread = p
    {
        float aK[8];
#pragma unroll
        for (int h = 0; h < 8; h++) aK[h] = 0.f;
#pragma unroll
        for (int h = 0; h < 8; h++) {
#pragma unroll 8
            for (int d = 0; d < 64; d++) {
                int i = h * 64 + d;
                aK[h] += g_WqT[i * 512 + tid] * kvec[i];
            }
        }
#pragma unroll
        for (int h = 0; h < 8; h++)
            g_kappa[((long)b * 512 + tid) * 64 + j * 8 + h] = aK[h] * SCALE_;
    }

    // vw: thread = o
    {
        float aV[8];
#pragma unroll
        for (int h = 0; h < 8; h++) aV[h] = 0.f;
#pragma unroll
        for (int h = 0; h < 8; h++) {
#pragma unroll 8
            for (int d = 0; d < 64; d++) {
                int i = h * 64 + d;
                aV[h] += Wout[i * 512 + tid] * vvec[i];
            }
        }
#pragma unroll
        for (int h = 0; h < 8; h++)
            g_vw[((long)b * 64 + j * 8 + h) * 512 + tid] = aV[h];
    }
}

// ---------------------------------------------------------------------------
// Kernel 5: sim + softmax. grid (32 nchunk, B), 256 thr.
// sim[n,c] = x[b,n,:]·kappa[b,:,c]  (SCALE already folded), softmax over j per h.
// ---------------------------------------------------------------------------
__global__ void __launch_bounds__(256)
simA_kernel(const float* __restrict__ x) {
    int nc = blockIdx.x, b = blockIdx.y;
    int n0 = nc * 64;
    int tid = threadIdx.x;
    int ty = tid >> 4, tx = tid & 15;

    __shared__ float xs[64 * 68];
    __shared__ float ks[64 * 68];

    float acc[4][4];
#pragma unroll
    for (int t = 0; t < 4; t++)
#pragma unroll
        for (int c = 0; c < 4; c++) acc[t][c] = 0.f;

    const float* xb = x + ((long)b * N_ + n0) * QD_;
    const float* kb = g_kappa + (long)b * QD_ * 64;

    for (int pc = 0; pc < 8; pc++) {
        int p0 = pc * 64;
#pragma unroll
        for (int kl = 0; kl < 4; kl++) {
            int f4 = tid + kl * 256;
            int row = f4 >> 4, c4 = (f4 & 15) * 4;
            float4 xv = *(const float4*)(xb + (long)row * QD_ + p0 + c4);
            *(float4*)&xs[row * 68 + c4] = xv;
            float4 kv = *(const float4*)(kb + (long)(p0 + row) * 64 + c4);
            *(float4*)&ks[row * 68 + c4] = kv;
        }
        __syncthreads();
#pragma unroll
        for (int kk = 0; kk < 64; kk += 4) {
            float4 av[4], bv[4];
#pragma unroll
            for (int t = 0; t < 4; t++) av[t] = *(const float4*)&xs[(ty * 4 + t) * 68 + kk];
#pragma unroll
            for (int cc = 0; cc < 4; cc++) bv[cc] = *(const float4*)&ks[(kk + cc) * 68 + tx * 4];
#pragma unroll
            for (int t = 0; t < 4; t++) {
                acc[t][0] += av[t].x * bv[0].x; acc[t][1] += av[t].x * bv[0].y;
                acc[t][2] += av[t].x * bv[0].z; acc[t][3] += av[t].x * bv[0].w;
                acc[t][0] += av[t].y * bv[1].x; acc[t][1] += av[t].y * bv[1].y;
                acc[t][2] += av[t].y * bv[1].z; acc[t][3] += av[t].y * bv[1].w;
                acc[t][0] += av[t].z * bv[2].x; acc[t][1] += av[t].z * bv[2].y;
                acc[t][2] += av[t].z * bv[2].z; acc[t][3] += av[t].z * bv[2].w;
                acc[t][0] += av[t].w * bv[3].x; acc[t][1] += av[t].w * bv[3].y;
                acc[t][2] += av[t].w * bv[3].z; acc[t][3] += av[t].w * bv[3].w;
            }
        }
        __syncthreads();
    }

    // write sim to smem
#pragma unroll
    for (int t = 0; t < 4; t++) {
        float4 v = make_float4(acc[t][0], acc[t][1], acc[t][2], acc[t][3]);
        *(float4*)&xs[(ty * 4 + t) * 68 + tx * 4] = v;
    }
    __syncthreads();

    // softmax over j per (token, head): 512 tasks, 2 per thread
#pragma unroll
    for (int s = 0; s < 2; s++) {
        int task = tid * 2 + s;
        int t = task >> 3, h = task & 7;
        float v[8];
#pragma unroll
        for (int jj = 0; jj < 8; jj++) v[jj] = xs[t * 68 + jj * 8 + h];
        float m = v[0];
#pragma unroll
        for (int jj = 1; jj < 8; jj++) m = fmaxf(m, v[jj]);
        float e[8], sum = 0.f;
#pragma unroll
        for (int jj = 0; jj < 8; jj++) { e[jj] = __expf(v[jj] - m); sum += e[jj]; }
        float inv = 1.f / sum;
        float* arow = g_a + ((long)b * N_ + n0 + t) * 64;
#pragma unroll
        for (int jj = 0; jj < 8; jj++) arow[jj * 8 + h] = e[jj] * inv;
    }
}

// ---------------------------------------------------------------------------
// Kernel 6: out[n, o] = sum_c a[n,c]*vw[c,o] + bout[o]
// grid (8 ochunk, 32 nchunk, B), 256 thr
// ---------------------------------------------------------------------------
__global__ void __launch_bounds__(256)
outB_kernel(float* __restrict__ out, const float* __restrict__ bout) {
    int oc = blockIdx.x, nc = blockIdx.y, b = blockIdx.z;
    int o0 = oc * 64, n0 = nc * 64;
    int tid = threadIdx.x;
    int ty = tid >> 4, tx = tid & 15;

    __shared__ float as_[64 * 68];
    __shared__ float vws[64 * 68];

#pragma unroll
    for (int kl = 0; kl < 4; kl++) {
        int f4 = tid + kl * 256;
        int row = f4 >> 4, c4 = (f4 & 15) * 4;
        float4 av = *(const float4*)(g_a + ((long)b * N_ + n0 + row) * 64 + c4);
        *(float4*)&as_[row * 68 + c4] = av;
        float4 wv = *(const float4*)(g_vw + ((long)b * 64 + row) * 512 + o0 + c4);
        *(float4*)&vws[row * 68 + c4] = wv;
    }
    __syncthreads();

    float acc[4][4];
#pragma unroll
    for (int t = 0; t < 4; t++)
#pragma unroll
        for (int o = 0; o < 4; o++) acc[t][o] = 0.f;

#pragma unroll
    for (int c = 0; c < 64; c += 4) {
        float4 av[4], bv[4];
#pragma unroll
        for (int t = 0; t < 4; t++) av[t] = *(const float4*)&as_[(ty * 4 + t) * 68 + c];
#pragma unroll
        for (int cc = 0; cc < 4; cc++) bv[cc] = *(const float4*)&vws[(c + cc) * 68 + tx * 4];
#pragma unroll
        for (int t = 0; t < 4; t++) {
            acc[t][0] += av[t].x * bv[0].x; acc[t][1] += av[t].x * bv[0].y;
            acc[t][2] += av[t].x * bv[0].z; acc[t][3] += av[t].x * bv[0].w;
            acc[t][0] += av[t].y * bv[1].x; acc[t][1] += av[t].y * bv[1].y;
            acc[t][2] += av[t].y * bv[1].z; acc[t][3] += av[t].y * bv[1].w;
            acc[t][0] += av[t].z * bv[2].x; acc[t][1] += av[t].z * bv[2].y;
            acc[t][2] += av[t].z * bv[2].z; acc[t][3] += av[t].z * bv[2].w;
            acc[t][0] += av[t].w * bv[3].x; acc[t][1] += av[t].w * bv[3].y;
            acc[t][2] += av[t].w * bv[3].z; acc[t][3] += av[t].w * bv[3].w;
        }
    }

    float4 bias = *(const float4*)(bout + o0 + tx * 4);
#pragma unroll
    for (int t = 0; t < 4; t++) {
        float4 r = make_float4(acc[t][0] + bias.x, acc[t][1] + bias.y,
                               acc[t][2] + bias.z, acc[t][3] + bias.w);
        *(float4*)(out + ((long)b * N_ + n0 + ty * 4 + t) * 512 + o0 + tx * 4) = r;
    }
}

// ---------------------------------------------------------------------------
// Launch
// ---------------------------------------------------------------------------
extern "C" void kernel_launch(void* const* d_in, const int* in_sizes, int n_in,
                              void* d_out, int out_size) {
    const float* x    = (const float*)d_in[0];
    const float* ctx  = (const float*)d_in[1];
    const float* Wq   = (const float*)d_in[2];
    const float* Wk   = (const float*)d_in[3];
    const float* Wv   = (const float*)d_in[4];
    const float* We   = (const float*)d_in[5];
    const float* Wout = (const float*)d_in[6];
    const float* bout = (const float*)d_in[7];
    float* out = (float*)d_out;

    transpose512<<<dim3(16, 16), 256>>>(Wq);
    e0_kernel<<<B_, 512>>>(x, Wq, We);
    dist_topk_kernel<<<dim3(DIST_BLOCKS, B_), 256>>>(ctx);
    topk_merge_kernel<<<B_, 32>>>();
    kvkv_kernel<<<64, 512>>>(ctx, Wk, Wv, Wout);
    simA_kernel<<<dim3(32, B_), 256>>>(x);
    outB_kernel<<<dim3(8, 32, B_), 256>>>(out, bout);
}

// round 3
// speedup vs baseline: 2.4321x; 1.5877x over previous
#include <cuda_runtime.h>
#include <math.h>

// ---------------------------------------------------------------------------
// Problem constants
// ---------------------------------------------------------------------------
#define B_     8
#define N_     2048
#define M_     32768
#define QD_    512
#define DR_    256
#define D_     512
#define H_     8
#define DH_    64
#define INNER_ 512
#define TOPK_  8
#define SCALE_ 0.125f

#define DIST_BLOCKS 128   // chunks per batch (256 rows each)
#define NCAND (DIST_BLOCKS * TOPK_)   // 1024 candidates per batch

// ---------------------------------------------------------------------------
// Scratch
// ---------------------------------------------------------------------------
__device__ float g_e0[B_ * DR_];
__device__ float g_cand_d2[B_ * NCAND];
__device__ int   g_cand_idx[B_ * NCAND];
__device__ int   g_topk_idx[B_ * TOPK_];
__device__ float g_WqT[QD_ * INNER_];          // WqT[i][p] = Wq[p][i]
__device__ float g_kappa[B_ * QD_ * 64];       // [b][p][c], c=j*8+h (SCALE folded)
__device__ float g_vw[B_ * 64 * INNER_];       // [b][c][o]
__device__ float g_a[B_ * N_ * 64];            // attention weights [b][n][c]

// ---------------------------------------------------------------------------
// Kernel 0: transpose Wq -> g_WqT
// ---------------------------------------------------------------------------
__global__ void transpose512(const float* __restrict__ Wq) {
    __shared__ float tile[32][33];
    int bx = blockIdx.x * 32, by = blockIdx.y * 32;
    int tx = threadIdx.x & 31, ty = threadIdx.x >> 5;
#pragma unroll
    for (int r = ty; r < 32; r += 8)
        tile[r][tx] = Wq[(by + r) * 512 + bx + tx];
    __syncthreads();
#pragma unroll
    for (int r = ty; r < 32; r += 8)
        g_WqT[(bx + r) * 512 + by + tx] = tile[tx][r];
}

// ---------------------------------------------------------------------------
// Kernel 1: e0[b,:] = (x[b,0,:] @ Wq) @ We   — deep unroll for MLP
// ---------------------------------------------------------------------------
__global__ void e0_kernel(const float* __restrict__ x,
                          const float* __restrict__ Wq,
                          const float* __restrict__ We) {
    int b = blockIdx.x;
    int tid = threadIdx.x;  // 512
    __shared__ float xs[QD_];
    __shared__ float q0[QD_];

    xs[tid] = x[(long)b * N_ * QD_ + tid];
    __syncthreads();

    {
        float acc = 0.f;
#pragma unroll 16
        for (int c = 0; c < QD_; c++)
            acc += xs[c] * Wq[c * INNER_ + tid];
        q0[tid] = acc;
    }
    __syncthreads();

    if (tid < DR_) {
        float acc = 0.f;
#pragma unroll 16
        for (int c = 0; c < INNER_; c++)
            acc += q0[c] * We[c * DR_ + tid];
        g_e0[b * DR_ + tid] = acc;
    }
}

// ---------------------------------------------------------------------------
// Kernel 2: distance scan + local top-8. grid (DIST_BLOCKS, B), 256 thr.
// Warp-per-row, 32 rows per warp.
// ---------------------------------------------------------------------------
__global__ void dist_topk_kernel(const float* __restrict__ ctx) {
    int b = blockIdx.y;
    int chunk = blockIdx.x;
    int tid = threadIdx.x;
    int warp = tid >> 5, lane = tid & 31;

    __shared__ float es[DR_];
    __shared__ float s_d2[8][TOPK_];
    __shared__ int   s_ix[8][TOPK_];

    if (tid < DR_) es[tid] = g_e0[b * DR_ + tid];
    __syncthreads();

    const float4* e4 = (const float4*)es;
    float4 ea = e4[lane];
    float4 eb = e4[lane + 32];

    float best[TOPK_];
    int   bidx[TOPK_];
#pragma unroll
    for (int i = 0; i < TOPK_; i++) { best[i] = 3.0e38f; bidx[i] = -1; }

    int row0 = chunk * 256 + warp * 32;
#pragma unroll 2
    for (int r = 0; r < 32; r++) {
        int row = row0 + r;
        const float4* crow = (const float4*)(ctx + ((long)b * M_ + row) * D_);
        float4 ca = crow[lane];
        float4 cb = crow[lane + 32];
        float dx, d2 = 0.f;
        dx = ca.x - ea.x; d2 += dx * dx;
        dx = ca.y - ea.y; d2 += dx * dx;
        dx = ca.z - ea.z; d2 += dx * dx;
        dx = ca.w - ea.w; d2 += dx * dx;
        dx = cb.x - eb.x; d2 += dx * dx;
        dx = cb.y - eb.y; d2 += dx * dx;
        dx = cb.z - eb.z; d2 += dx * dx;
        dx = cb.w - eb.w; d2 += dx * dx;
#pragma unroll
        for (int off = 16; off; off >>= 1)
            d2 += __shfl_down_sync(0xffffffffu, d2, off);
        if (lane == 0 && d2 < best[TOPK_ - 1]) {
            int p = TOPK_ - 1;
            while (p > 0 && best[p - 1] > d2) {
                best[p] = best[p - 1]; bidx[p] = bidx[p - 1]; p--;
            }
            best[p] = d2; bidx[p] = row;
        }
    }

    if (lane == 0) {
#pragma unroll
        for (int i = 0; i < TOPK_; i++) { s_d2[warp][i] = best[i]; s_ix[warp][i] = bidx[i]; }
    }
    __syncthreads();

    if (tid == 0) {
        float fb[TOPK_]; int fi[TOPK_];
#pragma unroll
        for (int i = 0; i < TOPK_; i++) { fb[i] = 3.0e38f; fi[i] = -1; }
        for (int w = 0; w < 8; w++)
            for (int i = 0; i < TOPK_; i++) {
                float d2 = s_d2[w][i];
                if (d2 < fb[TOPK_ - 1]) {
                    int ix = s_ix[w][i];
                    int p = TOPK_ - 1;
                    while (p > 0 && fb[p - 1] > d2) {
                        fb[p] = fb[p - 1]; fi[p] = fi[p - 1]; p--;
                    }
                    fb[p] = d2; fi[p] = ix;
                }
            }
        int off = (b * DIST_BLOCKS + chunk) * TOPK_;
        for (int i = 0; i < TOPK_; i++) { g_cand_d2[off + i] = fb[i]; g_cand_idx[off + i] = fi[i]; }
    }
}

// ---------------------------------------------------------------------------
// Kernel 3: parallel merge -> global per-batch top-8 (u64 keys, argmin x8)
// grid B, 256 threads
// ---------------------------------------------------------------------------
__device__ __forceinline__ unsigned long long u64min(unsigned long long a,
                                                     unsigned long long b) {
    return a < b ? a : b;
}
__global__ void __launch_bounds__(256)
topk_merge_kernel() {
    int b = blockIdx.x;
    int tid = threadIdx.x;
    __shared__ unsigned long long keys[NCAND];
    __shared__ unsigned long long red[256];

    int base = b * NCAND;
    for (int i = tid; i < NCAND; i += 256) {
        float d2 = g_cand_d2[base + i];
        int ix = g_cand_idx[base + i];
        unsigned long long k =
            ((unsigned long long)__float_as_uint(d2) << 32) | (unsigned int)ix;
        if (ix < 0) k = ~0ULL;
        keys[i] = k;
    }
    __syncthreads();

    for (int sel = 0; sel < TOPK_; sel++) {
        unsigned long long m = ~0ULL;
        for (int i = tid; i < NCAND; i += 256) m = u64min(m, keys[i]);
        red[tid] = m;
        __syncthreads();
#pragma unroll
        for (int s = 128; s > 0; s >>= 1) {
            if (tid < s) red[tid] = u64min(red[tid], red[tid + s]);
            __syncthreads();
        }
        unsigned long long w = red[0];
        if (tid == 0)
            g_topk_idx[b * TOPK_ + sel] = (int)(unsigned int)(w & 0xffffffffu);
        for (int i = tid; i < NCAND; i += 256)
            if (keys[i] == w) keys[i] = ~0ULL;
        __syncthreads();
    }
}

// ---------------------------------------------------------------------------
// Kernel 4: fused kv + kappa + vw.  grid (64 bj, 4 slice), 512 thr.
// Each block: gather row, k=labels@Wk, v=reps@Wv (full, cheap);
// then kappa/vw for a 128-wide p/o slice, 2 heads per thread.
// ---------------------------------------------------------------------------
__global__ void __launch_bounds__(512)
kvkv_kernel(const float* __restrict__ ctx,
            const float* __restrict__ Wk,
            const float* __restrict__ Wv,
            const float* __restrict__ Wout) {
    int bj = blockIdx.x;
    int slice = blockIdx.y;
    int b = bj >> 3, j = bj & 7;
    int tid = threadIdx.x;  // 512

    __shared__ float labels[DR_];
    __shared__ float reps[DR_];
    __shared__ float kvec[INNER_];
    __shared__ float vvec[INNER_];

    int row = g_topk_idx[bj];
    const float* crow = ctx + ((long)b * M_ + row) * D_;
    if (tid < 256) reps[tid] = crow[tid];
    else           labels[tid - 256] = crow[tid];
    __syncthreads();

    {
        float ak = 0.f, av = 0.f;
#pragma unroll 8
        for (int r = 0; r < DR_; r++) {
            float l = labels[r], rr = reps[r];
            ak += l * Wk[r * INNER_ + tid];
            av += rr * Wv[r * INNER_ + tid];
        }
        kvec[tid] = ak;
        vvec[tid] = av;
    }
    __syncthreads();

    int hp = tid >> 7;           // 0..3 -> heads hp and hp+4
    int pl = tid & 127;
    int p = slice * 128 + pl;    // p (for kappa) == o (for vw)

    // kappa
    {
        float aK0 = 0.f, aK1 = 0.f;
#pragma unroll 8
        for (int d = 0; d < 64; d++) {
            int i0 = hp * 64 + d;
            int i1 = (hp + 4) * 64 + d;
            aK0 += g_WqT[i0 * 512 + p] * kvec[i0];
            aK1 += g_WqT[i1 * 512 + p] * kvec[i1];
        }
        long kb = ((long)b * 512 + p) * 64 + j * 8;
        g_kappa[kb + hp]     = aK0 * SCALE_;
        g_kappa[kb + hp + 4] = aK1 * SCALE_;
    }

    // vw
    {
        float aV0 = 0.f, aV1 = 0.f;
#pragma unroll 8
        for (int d = 0; d < 64; d++) {
            int i0 = hp * 64 + d;
            int i1 = (hp + 4) * 64 + d;
            aV0 += Wout[i0 * 512 + p] * vvec[i0];
            aV1 += Wout[i1 * 512 + p] * vvec[i1];
        }
        g_vw[((long)b * 64 + j * 8 + hp) * 512 + p]     = aV0;
        g_vw[((long)b * 64 + j * 8 + hp + 4) * 512 + p] = aV1;
    }
}

// ---------------------------------------------------------------------------
// Kernel 5: sim + softmax. grid (16 nchunk, B), 256 thr. M-tile=128 tokens.
// sim[n,c] = x[b,n,:]·kappa[b,:,c]; softmax over j per (token, head).
// ---------------------------------------------------------------------------
__global__ void __launch_bounds__(256)
simA_kernel(const float* __restrict__ x) {
    int nc = blockIdx.x, b = blockIdx.y;
    int n0 = nc * 128;
    int tid = threadIdx.x;
    int ty = tid >> 4, tx = tid & 15;   // ty: 8-row group, tx: 4-col group

    __shared__ float xs[128 * 68];
    __shared__ float ks[64 * 68];

    float acc[8][4];
#pragma unroll
    for (int t = 0; t < 8; t++)
#pragma unroll
        for (int c = 0; c < 4; c++) acc[t][c] = 0.f;

    const float* xb = x + ((long)b * N_ + n0) * QD_;
    const float* kb = g_kappa + (long)b * QD_ * 64;

    for (int pc = 0; pc < 8; pc++) {
        int p0 = pc * 64;
#pragma unroll
        for (int l = 0; l < 8; l++) {
            int f = tid + l * 256;
            int row = f >> 4, c4 = (f & 15) * 4;
            *(float4*)&xs[row * 68 + c4] =
                *(const float4*)(xb + (long)row * QD_ + p0 + c4);
        }
#pragma unroll
        for (int l = 0; l < 4; l++) {
            int f = tid + l * 256;
            int row = f >> 4, c4 = (f & 15) * 4;
            *(float4*)&ks[row * 68 + c4] =
                *(const float4*)(kb + (long)(p0 + row) * 64 + c4);
        }
        __syncthreads();
#pragma unroll
        for (int kk = 0; kk < 64; kk += 4) {
            float4 av[8], bv[4];
#pragma unroll
            for (int t = 0; t < 8; t++)
                av[t] = *(const float4*)&xs[(ty * 8 + t) * 68 + kk];
#pragma unroll
            for (int cc = 0; cc < 4; cc++)
                bv[cc] = *(const float4*)&ks[(kk + cc) * 68 + tx * 4];
#pragma unroll
            for (int t = 0; t < 8; t++) {
                acc[t][0] += av[t].x * bv[0].x; acc[t][1] += av[t].x * bv[0].y;
                acc[t][2] += av[t].x * bv[0].z; acc[t][3] += av[t].x * bv[0].w;
                acc[t][0] += av[t].y * bv[1].x; acc[t][1] += av[t].y * bv[1].y;
                acc[t][2] += av[t].y * bv[1].z; acc[t][3] += av[t].y * bv[1].w;
                acc[t][0] += av[t].z * bv[2].x; acc[t][1] += av[t].z * bv[2].y;
                acc[t][2] += av[t].z * bv[2].z; acc[t][3] += av[t].z * bv[2].w;
                acc[t][0] += av[t].w * bv[3].x; acc[t][1] += av[t].w * bv[3].y;
                acc[t][2] += av[t].w * bv[3].z; acc[t][3] += av[t].w * bv[3].w;
            }
        }
        __syncthreads();
    }

    // dump sim into xs
#pragma unroll
    for (int t = 0; t < 8; t++) {
        float4 v = make_float4(acc[t][0], acc[t][1], acc[t][2], acc[t][3]);
        *(float4*)&xs[(ty * 8 + t) * 68 + tx * 4] = v;
    }
    __syncthreads();

    // softmax: 128 tokens x 8 heads = 1024 tasks, 4 per thread
#pragma unroll
    for (int s = 0; s < 4; s++) {
        int task = s * 256 + tid;
        int t = task >> 3, h = task & 7;
        float v[8];
#pragma unroll
        for (int jj = 0; jj < 8; jj++) v[jj] = xs[t * 68 + jj * 8 + h];
        float m = v[0];
#pragma unroll
        for (int jj = 1; jj < 8; jj++) m = fmaxf(m, v[jj]);
        float e[8], sum = 0.f;
#pragma unroll
        for (int jj = 0; jj < 8; jj++) { e[jj] = __expf(v[jj] - m); sum += e[jj]; }
        float inv = 1.f / sum;
        float* arow = g_a + ((long)b * N_ + n0 + t) * 64;
#pragma unroll
        for (int jj = 0; jj < 8; jj++) arow[jj * 8 + h] = e[jj] * inv;
    }
}

// ---------------------------------------------------------------------------
// Kernel 6: out[n,o] = sum_c a[n,c]*vw[c,o] + bout[o]
// grid (8 oc, 32 nc, B), 256 thr
// ---------------------------------------------------------------------------
__global__ void __launch_bounds__(256)
outB_kernel(float* __restrict__ out, const float* __restrict__ bout) {
    int oc = blockIdx.x, nc = blockIdx.y, b = blockIdx.z;
    int o0 = oc * 64, n0 = nc * 64;
    int tid = threadIdx.x;
    int ty = tid >> 4, tx = tid & 15;

    __shared__ float as_[64 * 68];
    __shared__ float vws[64 * 68];

#pragma unroll
    for (int l = 0; l < 4; l++) {
        int f = tid + l * 256;
        int row = f >> 4, c4 = (f & 15) * 4;
        *(float4*)&as_[row * 68 + c4] =
            *(const float4*)(g_a + ((long)b * N_ + n0 + row) * 64 + c4);
        *(float4*)&vws[row * 68 + c4] =
            *(const float4*)(g_vw + ((long)b * 64 + row) * 512 + o0 + c4);
    }
    __syncthreads();

    float acc[4][4];
#pragma unroll
    for (int t = 0; t < 4; t++)
#pragma unroll
        for (int o = 0; o < 4; o++) acc[t][o] = 0.f;

#pragma unroll
    for (int c = 0; c < 64; c += 4) {
        float4 av[4], bv[4];
#pragma unroll
        for (int t = 0; t < 4; t++) av[t] = *(const float4*)&as_[(ty * 4 + t) * 68 + c];
#pragma unroll
        for (int cc = 0; cc < 4; cc++) bv[cc] = *(const float4*)&vws[(c + cc) * 68 + tx * 4];
#pragma unroll
        for (int t = 0; t < 4; t++) {
            acc[t][0] += av[t].x * bv[0].x; acc[t][1] += av[t].x * bv[0].y;
            acc[t][2] += av[t].x * bv[0].z; acc[t][3] += av[t].x * bv[0].w;
            acc[t][0] += av[t].y * bv[1].x; acc[t][1] += av[t].y * bv[1].y;
            acc[t][2] += av[t].y * bv[1].z; acc[t][3] += av[t].y * bv[1].w;
            acc[t][0] += av[t].z * bv[2].x; acc[t][1] += av[t].z * bv[2].y;
            acc[t][2] += av[t].z * bv[2].z; acc[t][3] += av[t].z * bv[2].w;
            acc[t][0] += av[t].w * bv[3].x; acc[t][1] += av[t].w * bv[3].y;
            acc[t][2] += av[t].w * bv[3].z; acc[t][3] += av[t].w * bv[3].w;
        }
    }

    float4 bias = *(const float4*)(bout + o0 + tx * 4);
#pragma unroll
    for (int t = 0; t < 4; t++) {
        float4 r = make_float4(acc[t][0] + bias.x, acc[t][1] + bias.y,
                               acc[t][2] + bias.z, acc[t][3] + bias.w);
        *(float4*)(out + ((long)b * N_ + n0 + ty * 4 + t) * 512 + o0 + tx * 4) = r;
    }
}

// ---------------------------------------------------------------------------
// Launch
// ---------------------------------------------------------------------------
extern "C" void kernel_launch(void* const* d_in, const int* in_sizes, int n_in,
                              void* d_out, int out_size) {
    const float* x    = (const float*)d_in[0];
    const float* ctx  = (const float*)d_in[1];
    const float* Wq   = (const float*)d_in[2];
    const float* Wk   = (const float*)d_in[3];
    const float* Wv   = (const float*)d_in[4];
    const float* We   = (const float*)d_in[5];
    const float* Wout = (const float*)d_in[6];
    const float* bout = (const float*)d_in[7];
    float* out = (float*)d_out;

    transpose512<<<dim3(16, 16), 256>>>(Wq);
    e0_kernel<<<B_, 512>>>(x, Wq, We);
    dist_topk_kernel<<<dim3(DIST_BLOCKS, B_), 256>>>(ctx);
    topk_merge_kernel<<<B_, 256>>>();
    kvkv_kernel<<<dim3(64, 4), 512>>>(ctx, Wk, Wv, Wout);
    simA_kernel<<<dim3(16, B_), 256>>>(x);
    outB_kernel<<<dim3(8, 32, B_), 256>>>(out, bout);
}

// round 4
// speedup vs baseline: 2.4927x; 1.0249x over previous
#include <cuda_runtime.h>
#include <math.h>

// ---------------------------------------------------------------------------
// Problem constants
// ---------------------------------------------------------------------------
#define B_     8
#define N_     2048
#define M_     32768
#define QD_    512
#define DR_    256
#define D_     512
#define H_     8
#define DH_    64
#define INNER_ 512
#define TOPK_  8
#define SCALE_ 0.125f

#define DIST_BLOCKS 128   // chunks per batch (256 rows each)
#define NCAND (DIST_BLOCKS * TOPK_)   // 1024 candidates per batch

// ---------------------------------------------------------------------------
// Scratch
// ---------------------------------------------------------------------------
__device__ float g_e0[B_ * DR_];
__device__ float g_cand_d2[B_ * NCAND];
__device__ int   g_cand_idx[B_ * NCAND];
__device__ int   g_topk_idx[B_ * TOPK_];
__device__ float g_WqT[QD_ * INNER_];          // WqT[i][p] = Wq[p][i]
__device__ float g_kappa[B_ * QD_ * 64];       // [b][p][c], c=j*8+h (SCALE folded)
__device__ float g_vw[B_ * 64 * INNER_];       // [b][c][o]
__device__ float g_a[B_ * N_ * 64];            // attention weights [b][n][c]

// ---------------------------------------------------------------------------
// Kernel 0: transpose Wq -> g_WqT
// ---------------------------------------------------------------------------
__global__ void transpose512(const float* __restrict__ Wq) {
    __shared__ float tile[32][33];
    int bx = blockIdx.x * 32, by = blockIdx.y * 32;
    int tx = threadIdx.x & 31, ty = threadIdx.x >> 5;
#pragma unroll
    for (int r = ty; r < 32; r += 8)
        tile[r][tx] = Wq[(by + r) * 512 + bx + tx];
    __syncthreads();
#pragma unroll
    for (int r = ty; r < 32; r += 8)
        g_WqT[(bx + r) * 512 + by + tx] = tile[tx][r];
}

// ---------------------------------------------------------------------------
// Kernel 1: e0[b,:] = (x[b,0,:] @ Wq) @ We   — deep unroll for MLP
// ---------------------------------------------------------------------------
__global__ void e0_kernel(const float* __restrict__ x,
                          const float* __restrict__ Wq,
                          const float* __restrict__ We) {
    int b = blockIdx.x;
    int tid = threadIdx.x;  // 512
    __shared__ float xs[QD_];
    __shared__ float q0[QD_];

    xs[tid] = x[(long)b * N_ * QD_ + tid];
    __syncthreads();

    {
        float acc = 0.f;
#pragma unroll 16
        for (int c = 0; c < QD_; c++)
            acc += xs[c] * Wq[c * INNER_ + tid];
        q0[tid] = acc;
    }
    __syncthreads();

    if (tid < DR_) {
        float acc = 0.f;
#pragma unroll 16
        for (int c = 0; c < INNER_; c++)
            acc += q0[c] * We[c * DR_ + tid];
        g_e0[b * DR_ + tid] = acc;
    }
}

// ---------------------------------------------------------------------------
// Kernel 2: distance scan + local top-8. grid (DIST_BLOCKS, B), 256 thr.
// Warp-per-row, 32 rows per warp.
// ---------------------------------------------------------------------------
__global__ void dist_topk_kernel(const float* __restrict__ ctx) {
    int b = blockIdx.y;
    int chunk = blockIdx.x;
    int tid = threadIdx.x;
    int warp = tid >> 5, lane = tid & 31;

    __shared__ float es[DR_];
    __shared__ float s_d2[8][TOPK_];
    __shared__ int   s_ix[8][TOPK_];

    if (tid < DR_) es[tid] = g_e0[b * DR_ + tid];
    __syncthreads();

    const float4* e4 = (const float4*)es;
    float4 ea = e4[lane];
    float4 eb = e4[lane + 32];

    float best[TOPK_];
    int   bidx[TOPK_];
#pragma unroll
    for (int i = 0; i < TOPK_; i++) { best[i] = 3.0e38f; bidx[i] = -1; }

    int row0 = chunk * 256 + warp * 32;
#pragma unroll 2
    for (int r = 0; r < 32; r++) {
        int row = row0 + r;
        const float4* crow = (const float4*)(ctx + ((long)b * M_ + row) * D_);
        float4 ca = crow[lane];
        float4 cb = crow[lane + 32];
        float dx, d2 = 0.f;
        dx = ca.x - ea.x; d2 += dx * dx;
        dx = ca.y - ea.y; d2 += dx * dx;
        dx = ca.z - ea.z; d2 += dx * dx;
        dx = ca.w - ea.w; d2 += dx * dx;
        dx = cb.x - eb.x; d2 += dx * dx;
        dx = cb.y - eb.y; d2 += dx * dx;
        dx = cb.z - eb.z; d2 += dx * dx;
        dx = cb.w - eb.w; d2 += dx * dx;
#pragma unroll
        for (int off = 16; off; off >>= 1)
            d2 += __shfl_down_sync(0xffffffffu, d2, off);
        if (lane == 0 && d2 < best[TOPK_ - 1]) {
            int p = TOPK_ - 1;
            while (p > 0 && best[p - 1] > d2) {
                best[p] = best[p - 1]; bidx[p] = bidx[p - 1]; p--;
            }
            best[p] = d2; bidx[p] = row;
        }
    }

    if (lane == 0) {
#pragma unroll
        for (int i = 0; i < TOPK_; i++) { s_d2[warp][i] = best[i]; s_ix[warp][i] = bidx[i]; }
    }
    __syncthreads();

    if (tid == 0) {
        float fb[TOPK_]; int fi[TOPK_];
#pragma unroll
        for (int i = 0; i < TOPK_; i++) { fb[i] = 3.0e38f; fi[i] = -1; }
        for (int w = 0; w < 8; w++)
            for (int i = 0; i < TOPK_; i++) {
                float d2 = s_d2[w][i];
                if (d2 < fb[TOPK_ - 1]) {
                    int ix = s_ix[w][i];
                    int p = TOPK_ - 1;
                    while (p > 0 && fb[p - 1] > d2) {
                        fb[p] = fb[p - 1]; fi[p] = fi[p - 1]; p--;
                    }
                    fb[p] = d2; fi[p] = ix;
                }
            }
        int off = (b * DIST_BLOCKS + chunk) * TOPK_;
        for (int i = 0; i < TOPK_; i++) { g_cand_d2[off + i] = fb[i]; g_cand_idx[off + i] = fi[i]; }
    }
}

// ---------------------------------------------------------------------------
// Kernel 3: parallel merge -> global per-batch top-8 (u64 keys, argmin x8)
// grid B, 256 threads
// ---------------------------------------------------------------------------
__device__ __forceinline__ unsigned long long u64min(unsigned long long a,
                                                     unsigned long long b) {
    return a < b ? a : b;
}
__global__ void __launch_bounds__(256)
topk_merge_kernel() {
    int b = blockIdx.x;
    int tid = threadIdx.x;
    __shared__ unsigned long long keys[NCAND];
    __shared__ unsigned long long red[256];

    int base = b * NCAND;
    for (int i = tid; i < NCAND; i += 256) {
        float d2 = g_cand_d2[base + i];
        int ix = g_cand_idx[base + i];
        unsigned long long k =
            ((unsigned long long)__float_as_uint(d2) << 32) | (unsigned int)ix;
        if (ix < 0) k = ~0ULL;
        keys[i] = k;
    }
    __syncthreads();

    for (int sel = 0; sel < TOPK_; sel++) {
        unsigned long long m = ~0ULL;
        for (int i = tid; i < NCAND; i += 256) m = u64min(m, keys[i]);
        red[tid] = m;
        __syncthreads();
#pragma unroll
        for (int s = 128; s > 0; s >>= 1) {
            if (tid < s) red[tid] = u64min(red[tid], red[tid + s]);
            __syncthreads();
        }
        unsigned long long w = red[0];
        if (tid == 0)
            g_topk_idx[b * TOPK_ + sel] = (int)(unsigned int)(w & 0xffffffffu);
        for (int i = tid; i < NCAND; i += 256)
            if (keys[i] == w) keys[i] = ~0ULL;
        __syncthreads();
    }
}

// ---------------------------------------------------------------------------
// Kernel 4: fused kv + kappa + vw.  grid (64 bj, 4 slice), 512 thr.
// Each block: gather row, k=labels@Wk, v=reps@Wv (full, cheap);
// then kappa/vw for a 128-wide p/o slice, 2 heads per thread.
// ---------------------------------------------------------------------------
__global__ void __launch_bounds__(512)
kvkv_kernel(const float* __restrict__ ctx,
            const float* __restrict__ Wk,
            const float* __restrict__ Wv,
            const float* __restrict__ Wout) {
    int bj = blockIdx.x;
    int slice = blockIdx.y;
    int b = bj >> 3, j = bj & 7;
    int tid = threadIdx.x;  // 512

    __shared__ float labels[DR_];
    __shared__ float reps[DR_];
    __shared__ float kvec[INNER_];
    __shared__ float vvec[INNER_];

    int row = g_topk_idx[bj];
    const float* crow = ctx + ((long)b * M_ + row) * D_;
    if (tid < 256) reps[tid] = crow[tid];
    else           labels[tid - 256] = crow[tid];
    __syncthreads();

    {
        float ak = 0.f, av = 0.f;
#pragma unroll 8
        for (int r = 0; r < DR_; r++) {
            float l = labels[r], rr = reps[r];
            ak += l * Wk[r * INNER_ + tid];
            av += rr * Wv[r * INNER_ + tid];
        }
        kvec[tid] = ak;
        vvec[tid] = av;
    }
    __syncthreads();

    int hp = tid >> 7;           // 0..3 -> heads hp and hp+4
    int pl = tid & 127;
    int p = slice * 128 + pl;    // p (for kappa) == o (for vw)

    // kappa
    {
        float aK0 = 0.f, aK1 = 0.f;
#pragma unroll 8
        for (int d = 0; d < 64; d++) {
            int i0 = hp * 64 + d;
            int i1 = (hp + 4) * 64 + d;
            aK0 += g_WqT[i0 * 512 + p] * kvec[i0];
            aK1 += g_WqT[i1 * 512 + p] * kvec[i1];
        }
        long kb = ((long)b * 512 + p) * 64 + j * 8;
        g_kappa[kb + hp]     = aK0 * SCALE_;
        g_kappa[kb + hp + 4] = aK1 * SCALE_;
    }

    // vw
    {
        float aV0 = 0.f, aV1 = 0.f;
#pragma unroll 8
        for (int d = 0; d < 64; d++) {
            int i0 = hp * 64 + d;
            int i1 = (hp + 4) * 64 + d;
            aV0 += Wout[i0 * 512 + p] * vvec[i0];
            aV1 += Wout[i1 * 512 + p] * vvec[i1];
        }
        g_vw[((long)b * 64 + j * 8 + hp) * 512 + p]     = aV0;
        g_vw[((long)b * 64 + j * 8 + hp + 4) * 512 + p] = aV1;
    }
}

// ---------------------------------------------------------------------------
// Kernel 5: sim + softmax. grid (16 nchunk, B), 256 thr. M-tile=128 tokens.
// sim[n,c] = x[b,n,:]·kappa[b,:,c]; softmax over j per (token, head).
// ---------------------------------------------------------------------------
__global__ void __launch_bounds__(256)
simA_kernel(const float* __restrict__ x) {
    int nc = blockIdx.x, b = blockIdx.y;
    int n0 = nc * 128;
    int tid = threadIdx.x;
    int ty = tid >> 4, tx = tid & 15;   // ty: 8-row group, tx: 4-col group

    __shared__ float xs[128 * 68];
    __shared__ float ks[64 * 68];

    float acc[8][4];
#pragma unroll
    for (int t = 0; t < 8; t++)
#pragma unroll
        for (int c = 0; c < 4; c++) acc[t][c] = 0.f;

    const float* xb = x + ((long)b * N_ + n0) * QD_;
    const float* kb = g_kappa + (long)b * QD_ * 64;

    for (int pc = 0; pc < 8; pc++) {
        int p0 = pc * 64;
#pragma unroll
        for (int l = 0; l < 8; l++) {
            int f = tid + l * 256;
            int row = f >> 4, c4 = (f & 15) * 4;
            *(float4*)&xs[row * 68 + c4] =
                *(const float4*)(xb + (long)row * QD_ + p0 + c4);
        }
#pragma unroll
        for (int l = 0; l < 4; l++) {
            int f = tid + l * 256;
            int row = f >> 4, c4 = (f & 15) * 4;
            *(float4*)&ks[row * 68 + c4] =
                *(const float4*)(kb + (long)(p0 + row) * 64 + c4);
        }
        __syncthreads();
#pragma unroll
        for (int kk = 0; kk < 64; kk += 4) {
            float4 av[8], bv[4];
#pragma unroll
            for (int t = 0; t < 8; t++)
                av[t] = *(const float4*)&xs[(ty * 8 + t) * 68 + kk];
#pragma unroll
            for (int cc = 0; cc < 4; cc++)
                bv[cc] = *(const float4*)&ks[(kk + cc) * 68 + tx * 4];
#pragma unroll
            for (int t = 0; t < 8; t++) {
                acc[t][0] += av[t].x * bv[0].x; acc[t][1] += av[t].x * bv[0].y;
                acc[t][2] += av[t].x * bv[0].z; acc[t][3] += av[t].x * bv[0].w;
                acc[t][0] += av[t].y * bv[1].x; acc[t][1] += av[t].y * bv[1].y;
                acc[t][2] += av[t].y * bv[1].z; acc[t][3] += av[t].y * bv[1].w;
                acc[t][0] += av[t].z * bv[2].x; acc[t][1] += av[t].z * bv[2].y;
                acc[t][2] += av[t].z * bv[2].z; acc[t][3] += av[t].z * bv[2].w;
                acc[t][0] += av[t].w * bv[3].x; acc[t][1] += av[t].w * bv[3].y;
                acc[t][2] += av[t].w * bv[3].z; acc[t][3] += av[t].w * bv[3].w;
            }
        }
        __syncthreads();
    }

    // dump sim into xs
#pragma unroll
    for (int t = 0; t < 8; t++) {
        float4 v = make_float4(acc[t][0], acc[t][1], acc[t][2], acc[t][3]);
        *(float4*)&xs[(ty * 8 + t) * 68 + tx * 4] = v;
    }
    __syncthreads();

    // softmax: 128 tokens x 8 heads = 1024 tasks, 4 per thread
#pragma unroll
    for (int s = 0; s < 4; s++) {
        int task = s * 256 + tid;
        int t = task >> 3, h = task & 7;
        float v[8];
#pragma unroll
        for (int jj = 0; jj < 8; jj++) v[jj] = xs[t * 68 + jj * 8 + h];
        float m = v[0];
#pragma unroll
        for (int jj = 1; jj < 8; jj++) m = fmaxf(m, v[jj]);
        float e[8], sum = 0.f;
#pragma unroll
        for (int jj = 0; jj < 8; jj++) { e[jj] = __expf(v[jj] - m); sum += e[jj]; }
        float inv = 1.f / sum;
        float* arow = g_a + ((long)b * N_ + n0 + t) * 64;
#pragma unroll
        for (int jj = 0; jj < 8; jj++) arow[jj * 8 + h] = e[jj] * inv;
    }
}

// ---------------------------------------------------------------------------
// Kernel 6: out[n,o] = sum_c a[n,c]*vw[c,o] + bout[o]
// grid (8 oc, 32 nc, B), 256 thr
// ---------------------------------------------------------------------------
__global__ void __launch_bounds__(256)
outB_kernel(float* __restrict__ out, const float* __restrict__ bout) {
    int oc = blockIdx.x, nc = blockIdx.y, b = blockIdx.z;
    int o0 = oc * 64, n0 = nc * 64;
    int tid = threadIdx.x;
    int ty = tid >> 4, tx = tid & 15;

    __shared__ float as_[64 * 68];
    __shared__ float vws[64 * 68];

#pragma unroll
    for (int l = 0; l < 4; l++) {
        int f = tid + l * 256;
        int row = f >> 4, c4 = (f & 15) * 4;
        *(float4*)&as_[row * 68 + c4] =
            *(const float4*)(g_a + ((long)b * N_ + n0 + row) * 64 + c4);
        *(float4*)&vws[row * 68 + c4] =
            *(const float4*)(g_vw + ((long)b * 64 + row) * 512 + o0 + c4);
    }
    __syncthreads();

    float acc[4][4];
#pragma unroll
    for (int t = 0; t < 4; t++)
#pragma unroll
        for (int o = 0; o < 4; o++) acc[t][o] = 0.f;

#pragma unroll
    for (int c = 0; c < 64; c += 4) {
        float4 av[4], bv[4];
#pragma unroll
        for (int t = 0; t < 4; t++) av[t] = *(const float4*)&as_[(ty * 4 + t) * 68 + c];
#pragma unroll
        for (int cc = 0; cc < 4; cc++) bv[cc] = *(const float4*)&vws[(c + cc) * 68 + tx * 4];
#pragma unroll
        for (int t = 0; t < 4; t++) {
            acc[t][0] += av[t].x * bv[0].x; acc[t][1] += av[t].x * bv[0].y;
            acc[t][2] += av[t].x * bv[0].z; acc[t][3] += av[t].x * bv[0].w;
            acc[t][0] += av[t].y * bv[1].x; acc[t][1] += av[t].y * bv[1].y;
            acc[t][2] += av[t].y * bv[1].z; acc[t][3] += av[t].y * bv[1].w;
            acc[t][0] += av[t].z * bv[2].x; acc[t][1] += av[t].z * bv[2].y;
            acc[t][2] += av[t].z * bv[2].z; acc[t][3] += av[t].z * bv[2].w;
            acc[t][0] += av[t].w * bv[3].x; acc[t][1] += av[t].w * bv[3].y;
            acc[t][2] += av[t].w * bv[3].z; acc[t][3] += av[t].w * bv[3].w;
        }
    }

    float4 bias = *(const float4*)(bout + o0 + tx * 4);
#pragma unroll
    for (int t = 0; t < 4; t++) {
        float4 r = make_float4(acc[t][0] + bias.x, acc[t][1] + bias.y,
                               acc[t][2] + bias.z, acc[t][3] + bias.w);
        *(float4*)(out + ((long)b * N_ + n0 + ty * 4 + t) * 512 + o0 + tx * 4) = r;
    }
}

// ---------------------------------------------------------------------------
// Launch
// ---------------------------------------------------------------------------
extern "C" void kernel_launch(void* const* d_in, const int* in_sizes, int n_in,
                              void* d_out, int out_size) {
    const float* x    = (const float*)d_in[0];
    const float* ctx  = (const float*)d_in[1];
    const float* Wq   = (const float*)d_in[2];
    const float* Wk   = (const float*)d_in[3];
    const float* Wv   = (const float*)d_in[4];
    const float* We   = (const float*)d_in[5];
    const float* Wout = (const float*)d_in[6];
    const float* bout = (const float*)d_in[7];
    float* out = (float*)d_out;

    transpose512<<<dim3(16, 16), 256>>>(Wq);
    e0_kernel<<<B_, 512>>>(x, Wq, We);
    dist_topk_kernel<<<dim3(DIST_BLOCKS, B_), 256>>>(ctx);
    topk_merge_kernel<<<B_, 256>>>();
    kvkv_kernel<<<dim3(64, 4), 512>>>(ctx, Wk, Wv, Wout);
    simA_kernel<<<dim3(16, B_), 256>>>(x);
    outB_kernel<<<dim3(8, 32, B_), 256>>>(out, bout);
}